// round 2
// baseline (speedup 1.0000x reference)
#include <cuda_runtime.h>

#define TT   1024
#define FF   2048
#define LL   128
#define HH   256
#define GG   384
#define NF   14
#define NFP  7
#define NTH  256
#define NCTA 147          // ceil(2048/14)
#define PSTR 9            // padded pair-stride (u64 units) to kill bank conflicts

typedef unsigned long long u64;

// k-major transposed weights (device scratch; no allocation)
__device__ float g_W1t[LL * HH];   // [k][j]  : W1t[k*256+j]  = W1[j][k]
__device__ float g_W2t[HH * LL];   // [j][k'] : W2t[j*128+k'] = W2[k'][j]
__device__ float g_Wht[LL * GG];   // [k][g]  : Wht[k*384+g]  = Whh[g][k]

// shared-memory layout (u64 units)
#define OFF_HS   0
#define OFF_A1   (128 * PSTR)              // 1152
#define OFF_GH0  (OFF_A1 + 256 * PSTR)     // 3456
#define OFF_GH1  (OFF_GH0 + 384 * PSTR)    // 6912
#define OFF_BP0  (OFF_GH1 + 384 * PSTR)    // 10368
#define OFF_BP1  (OFF_BP0 + 128 * PSTR)    // 11520
#define U64_CNT  (OFF_BP1 + 128 * PSTR)    // 12672
#define FREG_CNT 1568
#define SMEM_BYTES (U64_CNT * 8 + FREG_CNT * 4)   // 107648 B

__device__ __forceinline__ u64 pk2(float lo, float hi) {
    u64 r; asm("mov.b64 %0, {%1, %2};" : "=l"(r) : "f"(lo), "f"(hi)); return r;
}
__device__ __forceinline__ float2 up2(u64 v) {
    float2 r; asm("mov.b64 {%0, %1}, %2;" : "=f"(r.x), "=f"(r.y) : "l"(v)); return r;
}
__device__ __forceinline__ u64 fma2(u64 a, u64 b, u64 c) {
    u64 d; asm("fma.rn.f32x2 %0, %1, %2, %3;" : "=l"(d) : "l"(a), "l"(b), "l"(c)); return d;
}
__device__ __forceinline__ u64 add2(u64 a, u64 b) {
    u64 d; asm("add.rn.f32x2 %0, %1, %2;" : "=l"(d) : "l"(a), "l"(b)); return d;
}
__device__ __forceinline__ float sigm(float x) { return 1.0f / (1.0f + expf(-x)); }

__global__ void prep_kernel(const float* __restrict__ W1,
                            const float* __restrict__ W2,
                            const float* __restrict__ Whh) {
    int i = blockIdx.x * blockDim.x + threadIdx.x;
    if (i < HH * LL) { int j = i / LL, k = i % LL; g_W1t[k * HH + j] = W1[i]; }
    if (i < LL * HH) { int k = i / HH, j = i % HH; g_W2t[j * LL + k] = W2[i]; }
    if (i < GG * LL) { int g = i / LL, k = i % LL; g_Wht[k * GG + g] = Whh[i]; }
}

__global__ __launch_bounds__(NTH, 1)
void odernn_kernel(const float* __restrict__ times,
                   const float* __restrict__ vals,
                   const float* __restrict__ mask,
                   const float* __restrict__ b1,
                   const float* __restrict__ b2,
                   const float* __restrict__ Wih,
                   const float* __restrict__ bih,
                   const float* __restrict__ bhh,
                   float* __restrict__ out)
{
    extern __shared__ u64 sm[];
    float* fb   = (float*)(sm + U64_CNT);
    float* b1s  = fb;
    float* b2s  = fb + 256;
    float* bihs = fb + 384;
    float* wihs = fb + 768;
    float* bhhs = fb + 1152;
    float* xob  = fb + 1536;   // 16
    float* xms  = fb + 1552;   // 16

    const int tid = threadIdx.x;
    const int cta = blockIdx.x;

    for (int i = tid; i < 256; i += NTH) b1s[i] = b1[i];
    for (int i = tid; i < 128; i += NTH) b2s[i] = b2[i];
    for (int i = tid; i < 384; i += NTH) { bihs[i] = bih[i]; wihs[i] = Wih[i]; bhhs[i] = bhh[i]; }
    for (int i = tid; i < 128 * PSTR; i += NTH) sm[OFF_HS + i] = 0ull;   // h0 = 0
    __syncthreads();

    const int p   = tid & 127;
    const int hi  = tid >> 7;            // thread half
    const int fpa = hi ? 4 : 0;          // fp subset for elementwise phases
    const int fpb = hi ? 7 : 4;

    for (int t = 0; t < TT; t++) {
        // per-step scalars: obs/mask for this CTA's features (reverse time)
        if (tid < NF) {
            int fg = cta * NF + tid;
            long it = (long)(TT - 1 - t) * FF + fg;
            xob[tid] = (fg < FF) ? __ldg(vals + it) : 0.0f;
            xms[tid] = (fg < FF) ? __ldg(mask + it) : 0.0f;
        }
        float dt = 0.0f;
        if (t > 0) dt = __ldg(times + (TT - t)) - __ldg(times + (TT - 1 - t));

        // ---- Phase A: a1[f][j] = sum_k h[f][k] * W1[j][k]; tanh(+b1) -> A1
        {
            u64 acc[NFP];
            #pragma unroll
            for (int fp = 0; fp < NFP; fp++) acc[fp] = 0ull;
            const float* w = g_W1t + tid;        // column j = tid
            #pragma unroll 4
            for (int k = 0; k < LL; k++) {
                float wv = __ldg(w + k * HH);
                u64 w2 = pk2(wv, wv);
                const u64* hr = sm + OFF_HS + k * PSTR;
                #pragma unroll
                for (int fp = 0; fp < NFP; fp++) acc[fp] = fma2(hr[fp], w2, acc[fp]);
            }
            float bb = b1s[tid];
            u64* ar = sm + OFF_A1 + tid * PSTR;
            #pragma unroll
            for (int fp = 0; fp < NFP; fp++) {
                float2 v = up2(acc[fp]);
                ar[fp] = pk2(tanhf(v.x + bb), tanhf(v.y + bb));
            }
        }
        __syncthreads();

        // ---- Phase B: f_ode[f][k'] partials = sum_{j in half} A1[f][j] * W2[k'][j]
        {
            u64 acc[NFP];
            #pragma unroll
            for (int fp = 0; fp < NFP; fp++) acc[fp] = 0ull;
            const float* w = g_W2t + p;          // output k' = p
            const int j0 = hi * 128;
            #pragma unroll 4
            for (int j = j0; j < j0 + 128; j++) {
                float wv = __ldg(w + j * LL);
                u64 w2 = pk2(wv, wv);
                const u64* ar = sm + OFF_A1 + j * PSTR;
                #pragma unroll
                for (int fp = 0; fp < NFP; fp++) acc[fp] = fma2(ar[fp], w2, acc[fp]);
            }
            u64* bp = sm + (hi ? OFF_BP1 : OFF_BP0) + p * PSTR;
            #pragma unroll
            for (int fp = 0; fp < NFP; fp++) bp[fp] = acc[fp];
        }
        __syncthreads();

        // ---- ODE update: h += dt * (B0 + B1 + b2)   (dt==0 at t==0 => no-op)
        {
            float bb = b2s[p];
            for (int fp = fpa; fp < fpb; fp++) {
                float2 s  = up2(add2(sm[OFF_BP0 + p * PSTR + fp], sm[OFF_BP1 + p * PSTR + fp]));
                float2 hv = up2(sm[OFF_HS + p * PSTR + fp]);
                hv.x = fmaf(dt, s.x + bb, hv.x);
                hv.y = fmaf(dt, s.y + bb, hv.y);
                sm[OFF_HS + p * PSTR + fp] = pk2(hv.x, hv.y);
            }
        }
        __syncthreads();

        // ---- Phase C: gh[f][g] partials = sum_{k in half} h[f][k] * Whh[g][k]
        {
            u64 a0[NFP], a1a[NFP], a2a[NFP];
            #pragma unroll
            for (int fp = 0; fp < NFP; fp++) { a0[fp] = 0ull; a1a[fp] = 0ull; a2a[fp] = 0ull; }
            const int k0 = hi * 64;
            #pragma unroll 2
            for (int k = k0; k < k0 + 64; k++) {
                const float* wr = g_Wht + k * GG + p;
                float w0 = __ldg(wr), w1 = __ldg(wr + 128), w2v = __ldg(wr + 256);
                u64 W0 = pk2(w0, w0), W1p = pk2(w1, w1), W2p = pk2(w2v, w2v);
                const u64* hr = sm + OFF_HS + k * PSTR;
                #pragma unroll
                for (int fp = 0; fp < NFP; fp++) {
                    u64 h = hr[fp];
                    a0[fp]  = fma2(h, W0,  a0[fp]);
                    a1a[fp] = fma2(h, W1p, a1a[fp]);
                    a2a[fp] = fma2(h, W2p, a2a[fp]);
                }
            }
            u64* gh = sm + (hi ? OFF_GH1 : OFF_GH0);
            #pragma unroll
            for (int fp = 0; fp < NFP; fp++) {
                gh[p * PSTR + fp]         = a0[fp];
                gh[(p + 128) * PSTR + fp] = a1a[fp];
                gh[(p + 256) * PSTR + fp] = a2a[fp];
            }
        }
        __syncthreads();

        // ---- GRU gates + mask update
        {
            float br = bhhs[p], bz = bhhs[p + 128], bn = bhhs[p + 256];
            float wir = wihs[p], wiz = wihs[p + 128], win = wihs[p + 256];
            float bir = bihs[p], biz = bihs[p + 128], binn = bihs[p + 256];
            for (int fp = fpa; fp < fpb; fp++) {
                float2 ghr = up2(add2(sm[OFF_GH0 + p * PSTR + fp],         sm[OFF_GH1 + p * PSTR + fp]));
                float2 ghz = up2(add2(sm[OFF_GH0 + (p + 128) * PSTR + fp], sm[OFF_GH1 + (p + 128) * PSTR + fp]));
                float2 ghn = up2(add2(sm[OFF_GH0 + (p + 256) * PSTR + fp], sm[OFF_GH1 + (p + 256) * PSTR + fp]));
                float2 hv  = up2(sm[OFF_HS + p * PSTR + fp]);
                {
                    float x = xob[2 * fp], m = xms[2 * fp];
                    float r = sigm(fmaf(x, wir, bir) + ghr.x + br);
                    float z = sigm(fmaf(x, wiz, biz) + ghz.x + bz);
                    float n = tanhf(fmaf(x, win, binn) + r * (ghn.x + bn));
                    float hc = (1.0f - z) * n + z * hv.x;
                    hv.x = m * hc + (1.0f - m) * hv.x;
                }
                {
                    float x = xob[2 * fp + 1], m = xms[2 * fp + 1];
                    float r = sigm(fmaf(x, wir, bir) + ghr.y + br);
                    float z = sigm(fmaf(x, wiz, biz) + ghz.y + bz);
                    float n = tanhf(fmaf(x, win, binn) + r * (ghn.y + bn));
                    float hc = (1.0f - z) * n + z * hv.y;
                    hv.y = m * hc + (1.0f - m) * hv.y;
                }
                sm[OFF_HS + p * PSTR + fp] = pk2(hv.x, hv.y);
            }
        }
        __syncthreads();
    }

    // ---- store final h : out[f_global][k]
    const float* hf = (const float*)(sm + OFF_HS);   // float layout: [k][2*PSTR] with f at k*18+f
    for (int idx = tid; idx < NF * LL; idx += NTH) {
        int f = idx >> 7, k = idx & 127;
        int fg = cta * NF + f;
        if (fg < FF) out[fg * LL + k] = hf[k * 2 * PSTR + f];
    }
}

extern "C" void kernel_launch(void* const* d_in, const int* in_sizes, int n_in,
                              void* d_out, int out_size) {
    const float* times = (const float*)d_in[0];
    const float* vals  = (const float*)d_in[1];
    const float* mask  = (const float*)d_in[2];
    const float* W1    = (const float*)d_in[3];
    const float* b1    = (const float*)d_in[4];
    const float* W2    = (const float*)d_in[5];
    const float* b2    = (const float*)d_in[6];
    const float* Wih   = (const float*)d_in[7];
    const float* bih   = (const float*)d_in[8];
    const float* Whh   = (const float*)d_in[9];
    const float* bhh   = (const float*)d_in[10];
    float* out = (float*)d_out;

    (void)in_sizes; (void)n_in; (void)out_size;

    cudaFuncSetAttribute(odernn_kernel,
                         cudaFuncAttributeMaxDynamicSharedMemorySize, SMEM_BYTES);

    prep_kernel<<<(GG * LL + 255) / 256, 256>>>(W1, W2, Whh);
    odernn_kernel<<<NCTA, NTH, SMEM_BYTES>>>(times, vals, mask, b1, b2,
                                             Wih, bih, bhh, out);
}